// round 4
// baseline (speedup 1.0000x reference)
#include <cuda_runtime.h>
#include <cuda_bf16.h>
#include <cstdint>

// Problem constants (fixed by reference setup_inputs)
#define T_DIM   2048
#define B_DIM   16
#define H_DIM   1024
#define M_TOTAL (T_DIM * B_DIM)   // 32768 rows
#define W_ATT   3

// GEMM tiling
#define MT      128   // rows per CTA
#define NT      256   // W-columns per n-tile
#define KT      16    // reduction slab
#define KTP     18    // padded k-stride for transposed W tile (bank-conflict-free)
#define NTHREADS 512  // 16 warps: 4 (M) x 4 (N)

// Scratch: per-warp-column partial scores, summed in kernel 2.
__device__ float g_scoresPartial[4 * M_TOTAL];

#define MMA_BF16(c, a, b0v, b1v)                                              \
    asm volatile(                                                             \
        "mma.sync.aligned.m16n8k16.row.col.f32.bf16.bf16.f32 "                \
        "{%0,%1,%2,%3}, {%4,%5,%6,%7}, {%8,%9}, {%0,%1,%2,%3};\n"             \
        : "+f"((c)[0]), "+f"((c)[1]), "+f"((c)[2]), "+f"((c)[3])              \
        : "r"((a)[0]), "r"((a)[1]), "r"((a)[2]), "r"((a)[3]),                 \
          "r"(b0v), "r"(b1v))

// Kernel 1: scores[r] = sum_k tanh( sum_h X[r,h] * W[h,k] ) * proj[k]
// bf16 2-term split (3 mma passes: hi*hi + hi*lo + lo*hi) for ~fp32 accuracy.
__global__ __launch_bounds__(NTHREADS)
void scores_kernel(const float* __restrict__ X,
                   const float* __restrict__ Wm,
                   const float* __restrict__ proj)
{
    __shared__ __nv_bfloat16 XsHi[MT * KT];
    __shared__ __nv_bfloat16 XsLo[MT * KT];
    __shared__ __nv_bfloat16 WsHiT[NT * KTP];   // transposed: [n][k]
    __shared__ __nv_bfloat16 WsLoT[NT * KTP];
    __shared__ float projs[H_DIM];

    const int tid  = threadIdx.x;
    const int lane = tid & 31;
    const int wid  = tid >> 5;
    const int g    = lane >> 2;   // groupID (0..7)
    const int tg   = lane & 3;    // thread-in-group (0..3)
    const int wm   = wid & 3;     // warp M index (0..3) -> 32 rows each
    const int wn   = wid >> 2;    // warp N index (0..3) -> 64 cols each
    const int rowBase = blockIdx.x * MT;

    projs[tid]       = proj[tid];
    projs[tid + 512] = proj[tid + 512];

    float C[2][8][4];
#pragma unroll
    for (int im = 0; im < 2; ++im)
#pragma unroll
        for (int in_ = 0; in_ < 8; ++in_)
#pragma unroll
            for (int e = 0; e < 4; ++e) C[im][in_][e] = 0.0f;

    float acc[4] = {0.f, 0.f, 0.f, 0.f};

    // Per-thread load assignments
    const int xRow = rowBase + (tid >> 2);     // 128 rows, 4 threads each
    const int xQ   = (tid & 3) * 4;            // 4 floats per thread
    const int wKr  = tid >> 6;                 // 0..7 (and +8 for 2nd vec)
    const int wN4  = (tid & 63) * 4;           // 0..252

    float4 xr, wr0, wr1;

    for (int nt = 0; nt < H_DIM / NT; ++nt) {
        const int n0 = nt * NT;
        // preload kt = 0
        xr  = *(const float4*)(X  + (size_t)xRow * H_DIM + xQ);
        wr0 = *(const float4*)(Wm + (size_t)(wKr)     * H_DIM + n0 + wN4);
        wr1 = *(const float4*)(Wm + (size_t)(wKr + 8) * H_DIM + n0 + wN4);

#pragma unroll 1
        for (int kt = 0; kt < H_DIM / KT; ++kt) {
            __syncthreads();
            // split + store X slab
            {
                float xv[4] = {xr.x, xr.y, xr.z, xr.w};
                const int xbase = (tid >> 2) * KT + xQ;
#pragma unroll
                for (int j = 0; j < 4; ++j) {
                    __nv_bfloat16 h = __float2bfloat16(xv[j]);
                    __nv_bfloat16 l = __float2bfloat16(xv[j] - __bfloat162float(h));
                    XsHi[xbase + j] = h;
                    XsLo[xbase + j] = l;
                }
                float w0[4] = {wr0.x, wr0.y, wr0.z, wr0.w};
                float w1[4] = {wr1.x, wr1.y, wr1.z, wr1.w};
#pragma unroll
                for (int j = 0; j < 4; ++j) {
                    const int n = wN4 + j;
                    __nv_bfloat16 h0 = __float2bfloat16(w0[j]);
                    __nv_bfloat16 l0 = __float2bfloat16(w0[j] - __bfloat162float(h0));
                    __nv_bfloat16 h1 = __float2bfloat16(w1[j]);
                    __nv_bfloat16 l1 = __float2bfloat16(w1[j] - __bfloat162float(h1));
                    WsHiT[n * KTP + wKr]     = h0;
                    WsLoT[n * KTP + wKr]     = l0;
                    WsHiT[n * KTP + wKr + 8] = h1;
                    WsLoT[n * KTP + wKr + 8] = l1;
                }
            }
            if (kt < H_DIM / KT - 1) {
                const int k1 = (kt + 1) * KT;
                xr  = *(const float4*)(X  + (size_t)xRow * H_DIM + k1 + xQ);
                wr0 = *(const float4*)(Wm + (size_t)(k1 + wKr)     * H_DIM + n0 + wN4);
                wr1 = *(const float4*)(Wm + (size_t)(k1 + wKr + 8) * H_DIM + n0 + wN4);
            }
            __syncthreads();

            // A fragments (m16n8k16, row-major): row g(+8), cols 2tg(+1), +8(+9)
            uint32_t Ahi[2][4], Alo[2][4];
#pragma unroll
            for (int im = 0; im < 2; ++im) {
                const int r0 = wm * 32 + im * 16;
                Ahi[im][0] = *(const uint32_t*)&XsHi[(r0 + g) * KT + 2 * tg];
                Ahi[im][1] = *(const uint32_t*)&XsHi[(r0 + g + 8) * KT + 2 * tg];
                Ahi[im][2] = *(const uint32_t*)&XsHi[(r0 + g) * KT + 2 * tg + 8];
                Ahi[im][3] = *(const uint32_t*)&XsHi[(r0 + g + 8) * KT + 2 * tg + 8];
                Alo[im][0] = *(const uint32_t*)&XsLo[(r0 + g) * KT + 2 * tg];
                Alo[im][1] = *(const uint32_t*)&XsLo[(r0 + g + 8) * KT + 2 * tg];
                Alo[im][2] = *(const uint32_t*)&XsLo[(r0 + g) * KT + 2 * tg + 8];
                Alo[im][3] = *(const uint32_t*)&XsLo[(r0 + g + 8) * KT + 2 * tg + 8];
            }

#pragma unroll
            for (int in_ = 0; in_ < 8; ++in_) {
                const int n = wn * 64 + in_ * 8 + g;  // B col = groupID
                const uint32_t Bhi0 = *(const uint32_t*)&WsHiT[n * KTP + 2 * tg];
                const uint32_t Bhi1 = *(const uint32_t*)&WsHiT[n * KTP + 2 * tg + 8];
                const uint32_t Blo0 = *(const uint32_t*)&WsLoT[n * KTP + 2 * tg];
                const uint32_t Blo1 = *(const uint32_t*)&WsLoT[n * KTP + 2 * tg + 8];
#pragma unroll
                for (int im = 0; im < 2; ++im) {
                    MMA_BF16(C[im][in_], Ahi[im], Bhi0, Bhi1);
                    MMA_BF16(C[im][in_], Ahi[im], Blo0, Blo1);
                    MMA_BF16(C[im][in_], Alo[im], Bhi0, Bhi1);
                }
            }
        }

        // epilogue for this n-tile: tanh * proj, accumulate per-row partials
#pragma unroll
        for (int im = 0; im < 2; ++im) {
#pragma unroll
            for (int in_ = 0; in_ < 8; ++in_) {
                const int ncol = n0 + wn * 64 + in_ * 8 + 2 * tg;
                const float p0 = projs[ncol];
                const float p1 = projs[ncol + 1];
                acc[im * 2 + 0] += tanhf(C[im][in_][0]) * p0 + tanhf(C[im][in_][1]) * p1;
                acc[im * 2 + 1] += tanhf(C[im][in_][2]) * p0 + tanhf(C[im][in_][3]) * p1;
                C[im][in_][0] = 0.f; C[im][in_][1] = 0.f;
                C[im][in_][2] = 0.f; C[im][in_][3] = 0.f;
            }
        }
    }

    // reduce over tig lanes (same rows, disjoint cols)
#pragma unroll
    for (int i = 0; i < 4; ++i) {
        acc[i] += __shfl_xor_sync(0xffffffff, acc[i], 1);
        acc[i] += __shfl_xor_sync(0xffffffff, acc[i], 2);
    }
    if (tg == 0) {
#pragma unroll
        for (int i = 0; i < 4; ++i) {
            const int rl = (i >> 1) * 16 + (i & 1) * 8 + g;
            g_scoresPartial[wn * M_TOTAL + rowBase + wm * 32 + rl] = acc[i];
        }
    }
}

// Kernel 2: softmax over the 3-wide window + weighted sum; prefix copy for t<3.
__global__ __launch_bounds__(256)
void output_kernel(const float* __restrict__ X, float* __restrict__ out)
{
    const int row = blockIdx.x;        // t*B + b
    const int tid = threadIdx.x;       // 256 threads, one float4 each
    const int t   = row >> 4;          // B = 16
    const float4* Xi = (const float4*)X;
    float4* O = (float4*)out;

    if (t < W_ATT) {
        O[(size_t)row * 256 + tid] = Xi[(size_t)row * 256 + tid];
        return;
    }
    const int r0 = row - W_ATT * B_DIM;  // rows r0, r0+16, r0+32
    float s0 = g_scoresPartial[r0] + g_scoresPartial[M_TOTAL + r0]
             + g_scoresPartial[2 * M_TOTAL + r0] + g_scoresPartial[3 * M_TOTAL + r0];
    const int r1 = r0 + B_DIM;
    float s1 = g_scoresPartial[r1] + g_scoresPartial[M_TOTAL + r1]
             + g_scoresPartial[2 * M_TOTAL + r1] + g_scoresPartial[3 * M_TOTAL + r1];
    const int r2 = r0 + 2 * B_DIM;
    float s2 = g_scoresPartial[r2] + g_scoresPartial[M_TOTAL + r2]
             + g_scoresPartial[2 * M_TOTAL + r2] + g_scoresPartial[3 * M_TOTAL + r2];

    const float m  = fmaxf(s0, fmaxf(s1, s2));
    const float e0 = expf(s0 - m);
    const float e1 = expf(s1 - m);
    const float e2 = expf(s2 - m);
    const float inv = 1.0f / (e0 + e1 + e2);
    const float a0 = e0 * inv, a1 = e1 * inv, a2 = e2 * inv;

    const float4 x0 = Xi[(size_t)r0 * 256 + tid];
    const float4 x1 = Xi[(size_t)r1 * 256 + tid];
    const float4 x2 = Xi[(size_t)r2 * 256 + tid];
    float4 o;
    o.x = a0 * x0.x + a1 * x1.x + a2 * x2.x;
    o.y = a0 * x0.y + a1 * x1.y + a2 * x2.y;
    o.z = a0 * x0.z + a1 * x1.z + a2 * x2.z;
    o.w = a0 * x0.w + a1 * x1.w + a2 * x2.w;
    O[(size_t)row * 256 + tid] = o;
}

extern "C" void kernel_launch(void* const* d_in, const int* in_sizes, int n_in,
                              void* d_out, int out_size)
{
    const float* X    = (const float*)d_in[0];
    const float* Wm   = (const float*)d_in[1];
    const float* proj = (const float*)d_in[2];
    float* out        = (float*)d_out;

    scores_kernel<<<M_TOTAL / MT, NTHREADS>>>(X, Wm, proj);
    output_kernel<<<M_TOTAL, 256>>>(X, out);
}

// round 6
// speedup vs baseline: 2.0498x; 2.0498x over previous
#include <cuda_runtime.h>
#include <cuda_bf16.h>
#include <cstdint>

// ---------------- problem constants ----------------
#define T_DIM   2048
#define B_DIM   16
#define H_DIM   1024
#define M_TOTAL (T_DIM * B_DIM)     // 32768 rows
#define W_ATT   3

// ---------------- GEMM tiling ----------------
#define TILE_M   128
#define TILE_N   256
#define KC       64                  // k elems per chunk
#define NCHUNKS  (H_DIM / KC)        // 16
#define NTILES   (H_DIM / TILE_N)    // 4
#define MTILES   (M_TOTAL / TILE_M)  // 256
#define GEMM_THREADS 512

// SMEM row stride: 64 bf16 = 128B data, padded to 144B (bank-conflict-free ldmatrix)
#define ROWB     144
#define A_BYTES  (TILE_M * ROWB)     // 18432
#define B_BYTES  (TILE_N * ROWB)     // 36864
#define AHI_OFF  0
#define ALO_OFF  A_BYTES             // 18432
#define BHI_OFF  (2 * A_BYTES)       // 36864
#define BLO_OFF  (2 * A_BYTES + B_BYTES)  // 73728
#define STAGE_BYTES (2 * A_BYTES + 2 * B_BYTES)  // 110592
#define PROJ_OFF (2 * STAGE_BYTES)        // 221184 (256 floats)
#define RED_OFF  (PROJ_OFF + 1024)        // 222208 (512 floats)
#define SMEM_TOTAL_GEMM (RED_OFF + 2048)  // 224256

// ---------------- global scratch ----------------
__device__ __nv_bfloat16 g_xhi[(size_t)M_TOTAL * H_DIM];
__device__ __nv_bfloat16 g_xlo[(size_t)M_TOTAL * H_DIM];
__device__ __nv_bfloat16 g_whiT[(size_t)H_DIM * H_DIM];   // [n][k]
__device__ __nv_bfloat16 g_wloT[(size_t)H_DIM * H_DIM];
__device__ float g_part[NTILES * M_TOTAL];

// ---------------- helpers ----------------
__device__ __forceinline__ uint32_t smem_u32(const void* p) {
    uint32_t a;
    asm("{ .reg .u64 t; cvta.to.shared.u64 t, %1; cvt.u32.u64 %0, t; }" : "=r"(a) : "l"(p));
    return a;
}

__device__ __forceinline__ void cp16(uint32_t dst, const void* src) {
    asm volatile("cp.async.cg.shared.global [%0], [%1], 16;\n"
                 :: "r"(dst), "l"(__cvta_generic_to_global(src)) : "memory");
}
#define CP_COMMIT() asm volatile("cp.async.commit_group;" ::: "memory")
#define CP_WAIT0()  asm volatile("cp.async.wait_group 0;"  ::: "memory")
#define CP_WAIT1()  asm volatile("cp.async.wait_group 1;"  ::: "memory")

__device__ __forceinline__ void ldsm_x4(uint32_t* r, uint32_t addr) {
    asm volatile("ldmatrix.sync.aligned.m8n8.x4.shared.b16 {%0,%1,%2,%3}, [%4];"
                 : "=r"(r[0]), "=r"(r[1]), "=r"(r[2]), "=r"(r[3]) : "r"(addr));
}

#define MMA_BF16(c, a, b0v, b1v)                                              \
    asm volatile(                                                             \
        "mma.sync.aligned.m16n8k16.row.col.f32.bf16.bf16.f32 "                \
        "{%0,%1,%2,%3}, {%4,%5,%6,%7}, {%8,%9}, {%0,%1,%2,%3};\n"             \
        : "+f"((c)[0]), "+f"((c)[1]), "+f"((c)[2]), "+f"((c)[3])              \
        : "r"((a)[0]), "r"((a)[1]), "r"((a)[2]), "r"((a)[3]),                 \
          "r"(b0v), "r"(b1v))

// ---------------- convert kernels ----------------
__global__ __launch_bounds__(256)
void convert_x_kernel(const float* __restrict__ X)
{
    size_t i = (size_t)blockIdx.x * 256 + threadIdx.x;    // float4 index
    float4 v = ((const float4*)X)[i];
    float xv[4] = {v.x, v.y, v.z, v.w};
    __nv_bfloat16 h[4], l[4];
#pragma unroll
    for (int j = 0; j < 4; ++j) {
        h[j] = __float2bfloat16(xv[j]);
        l[j] = __float2bfloat16(xv[j] - __bfloat162float(h[j]));
    }
    __nv_bfloat162 ph0 = {h[0], h[1]}, ph1 = {h[2], h[3]};
    __nv_bfloat162 pl0 = {l[0], l[1]}, pl1 = {l[2], l[3]};
    uint2 uh, ul;
    uh.x = *(uint32_t*)&ph0; uh.y = *(uint32_t*)&ph1;
    ul.x = *(uint32_t*)&pl0; ul.y = *(uint32_t*)&pl1;
    ((uint2*)g_xhi)[i] = uh;
    ((uint2*)g_xlo)[i] = ul;
}

__global__ __launch_bounds__(1024)
void convert_w_kernel(const float* __restrict__ W)
{
    __shared__ float t[32][33];
    int x = blockIdx.x * 32 + threadIdx.x;   // n
    int y = blockIdx.y * 32 + threadIdx.y;   // k
    t[threadIdx.y][threadIdx.x] = W[(size_t)y * H_DIM + x];
    __syncthreads();
    int n  = blockIdx.x * 32 + threadIdx.y;
    int kk = blockIdx.y * 32 + threadIdx.x;
    float v = t[threadIdx.x][threadIdx.y];
    __nv_bfloat16 h = __float2bfloat16(v);
    __nv_bfloat16 l = __float2bfloat16(v - __bfloat162float(h));
    g_whiT[(size_t)n * H_DIM + kk] = h;
    g_wloT[(size_t)n * H_DIM + kk] = l;
}

// ---------------- GEMM + fused tanh/proj epilogue ----------------
__device__ __forceinline__ void load_stage(uint32_t sbStage, int rowBase, int n0,
                                           int k0, int tid)
{
    // A: 128 rows x 8 x 16B, hi + lo
#pragma unroll
    for (int i = 0; i < 2; ++i) {
        int c = tid + i * 512;
        int row = c >> 3, q = c & 7;
        size_t off = (size_t)(rowBase + row) * H_DIM + k0 + q * 8;
        uint32_t d = sbStage + row * ROWB + q * 16;
        cp16(d + AHI_OFF, g_xhi + off);
        cp16(d + ALO_OFF, g_xlo + off);
    }
    // B: 256 rows x 8 x 16B, hi + lo
#pragma unroll
    for (int i = 0; i < 4; ++i) {
        int c = tid + i * 512;
        int row = c >> 3, q = c & 7;
        size_t off = (size_t)(n0 + row) * H_DIM + k0 + q * 8;
        uint32_t d = sbStage + row * ROWB + q * 16;
        cp16(d + BHI_OFF, g_whiT + off);
        cp16(d + BLO_OFF, g_wloT + off);
    }
}

__global__ __launch_bounds__(GEMM_THREADS, 1)
void gemm_scores_kernel(const float* __restrict__ proj)
{
    extern __shared__ __align__(16) char smem_raw[];
    const uint32_t sb = smem_u32(smem_raw);
    const int tid  = threadIdx.x;
    const int lane = tid & 31;
    const int wid  = tid >> 5;
    const int g    = lane >> 2;
    const int tg   = lane & 3;
    const int wm   = wid & 3;     // warp M (0..3): rows wm*32..+32
    const int wn   = wid >> 2;    // warp N (0..3): cols wn*64..+64

    const int mt = blockIdx.x >> 2;
    const int nt = blockIdx.x & 3;
    const int rowBase = mt * TILE_M;
    const int n0 = nt * TILE_N;

    float* projs = (float*)(smem_raw + PROJ_OFF);
    float* red   = (float*)(smem_raw + RED_OFF);
    if (tid < 256) projs[tid] = proj[n0 + tid];

    float C[2][8][4];
#pragma unroll
    for (int im = 0; im < 2; ++im)
#pragma unroll
        for (int in_ = 0; in_ < 8; ++in_)
#pragma unroll
            for (int e = 0; e < 4; ++e) C[im][in_][e] = 0.0f;

    // per-lane ldmatrix base addresses (within a stage)
    // A: lane -> row (lane&15), k-half (lane>>4)
    const uint32_t aBaseRel = (uint32_t)((wm * 32 + (lane & 15)) * ROWB + (lane >> 4) * 16);
    // B: lane -> n row, k-half
    const uint32_t bBaseRel = (uint32_t)(BHI_OFF +
        (wn * 64 + (lane & 7) + ((lane >> 4) & 1) * 8) * ROWB + ((lane >> 3) & 1) * 16);

    load_stage(sb, rowBase, n0, 0, tid);
    CP_COMMIT();
    load_stage(sb + STAGE_BYTES, rowBase, n0, KC, tid);
    CP_COMMIT();

#pragma unroll 1
    for (int k = 0; k < NCHUNKS; ++k) {
        if (k < NCHUNKS - 1) { CP_WAIT1(); } else { CP_WAIT0(); }
        __syncthreads();

        const uint32_t sBase = sb + (uint32_t)(k & 1) * STAGE_BYTES;
        const uint32_t aB = sBase + aBaseRel;
        const uint32_t bB = sBase + bBaseRel;

#pragma unroll
        for (int ks = 0; ks < 4; ++ks) {
            uint32_t ah[2][4], al[2][4];
            ldsm_x4(ah[0], aB + AHI_OFF + ks * 32);
            ldsm_x4(ah[1], aB + AHI_OFF + 16 * ROWB + ks * 32);
            ldsm_x4(al[0], aB + ALO_OFF + ks * 32);
            ldsm_x4(al[1], aB + ALO_OFF + 16 * ROWB + ks * 32);
#pragma unroll
            for (int p = 0; p < 4; ++p) {
                uint32_t bh[4], bl[4];
                ldsm_x4(bh, bB + p * (16 * ROWB) + ks * 32);
                ldsm_x4(bl, bB + (BLO_OFF - BHI_OFF) + p * (16 * ROWB) + ks * 32);
#pragma unroll
                for (int im = 0; im < 2; ++im) {
                    MMA_BF16(C[im][2 * p],     ah[im], bh[0], bh[1]);
                    MMA_BF16(C[im][2 * p],     ah[im], bl[0], bl[1]);
                    MMA_BF16(C[im][2 * p],     al[im], bh[0], bh[1]);
                    MMA_BF16(C[im][2 * p + 1], ah[im], bh[2], bh[3]);
                    MMA_BF16(C[im][2 * p + 1], ah[im], bl[2], bl[3]);
                    MMA_BF16(C[im][2 * p + 1], al[im], bh[2], bh[3]);
                }
            }
        }
        __syncthreads();
        if (k + 2 < NCHUNKS) {
            load_stage(sb + (uint32_t)(k & 1) * STAGE_BYTES, rowBase, n0, (k + 2) * KC, tid);
            CP_COMMIT();
        }
    }

    // ---- epilogue: tanh * proj, reduce over columns ----
    float acc[4] = {0.f, 0.f, 0.f, 0.f};
#pragma unroll
    for (int im = 0; im < 2; ++im) {
#pragma unroll
        for (int in_ = 0; in_ < 8; ++in_) {
            const int col = wn * 64 + in_ * 8 + 2 * tg;
            const float p0 = projs[col];
            const float p1 = projs[col + 1];
            acc[im * 2 + 0] += tanhf(C[im][in_][0]) * p0 + tanhf(C[im][in_][1]) * p1;
            acc[im * 2 + 1] += tanhf(C[im][in_][2]) * p0 + tanhf(C[im][in_][3]) * p1;
        }
    }
#pragma unroll
    for (int i = 0; i < 4; ++i) {
        acc[i] += __shfl_xor_sync(0xffffffff, acc[i], 1);
        acc[i] += __shfl_xor_sync(0xffffffff, acc[i], 2);
    }
    if (tg == 0) {
#pragma unroll
        for (int i = 0; i < 4; ++i) {
            const int im = i >> 1, half = i & 1;
            const int row = wm * 32 + im * 16 + half * 8 + g;
            red[wn * 128 + row] = acc[i];
        }
    }
    __syncthreads();
    if (tid < 128) {
        float s = red[tid] + red[128 + tid] + red[256 + tid] + red[384 + tid];
        g_part[nt * M_TOTAL + rowBase + tid] = s;
    }
}

// ---------------- output: softmax over 3-window + weighted sum ----------------
__global__ __launch_bounds__(256)
void output_kernel(const float* __restrict__ X, float* __restrict__ out)
{
    const int row = blockIdx.x;        // t*B + b
    const int tid = threadIdx.x;
    const int t   = row >> 4;          // B = 16
    const float4* Xi = (const float4*)X;
    float4* O = (float4*)out;

    if (t < W_ATT) {
        O[(size_t)row * 256 + tid] = Xi[(size_t)row * 256 + tid];
        return;
    }
    const int r0 = row - W_ATT * B_DIM;
    const int r1 = r0 + B_DIM;
    const int r2 = r0 + 2 * B_DIM;
    float s0 = g_part[r0] + g_part[M_TOTAL + r0] + g_part[2 * M_TOTAL + r0] + g_part[3 * M_TOTAL + r0];
    float s1 = g_part[r1] + g_part[M_TOTAL + r1] + g_part[2 * M_TOTAL + r1] + g_part[3 * M_TOTAL + r1];
    float s2 = g_part[r2] + g_part[M_TOTAL + r2] + g_part[2 * M_TOTAL + r2] + g_part[3 * M_TOTAL + r2];

    const float m  = fmaxf(s0, fmaxf(s1, s2));
    const float e0 = expf(s0 - m);
    const float e1 = expf(s1 - m);
    const float e2 = expf(s2 - m);
    const float inv = 1.0f / (e0 + e1 + e2);
    const float a0 = e0 * inv, a1 = e1 * inv, a2 = e2 * inv;

    const float4 x0 = Xi[(size_t)r0 * 256 + tid];
    const float4 x1 = Xi[(size_t)r1 * 256 + tid];
    const float4 x2 = Xi[(size_t)r2 * 256 + tid];
    float4 o;
    o.x = a0 * x0.x + a1 * x1.x + a2 * x2.x;
    o.y = a0 * x0.y + a1 * x1.y + a2 * x2.y;
    o.z = a0 * x0.z + a1 * x1.z + a2 * x2.z;
    o.w = a0 * x0.w + a1 * x1.w + a2 * x2.w;
    O[(size_t)row * 256 + tid] = o;
}

// ---------------- launch ----------------
extern "C" void kernel_launch(void* const* d_in, const int* in_sizes, int n_in,
                              void* d_out, int out_size)
{
    const float* X    = (const float*)d_in[0];
    const float* Wm   = (const float*)d_in[1];
    const float* proj = (const float*)d_in[2];
    float* out        = (float*)d_out;

    cudaFuncSetAttribute(gemm_scores_kernel,
                         cudaFuncAttributeMaxDynamicSharedMemorySize,
                         SMEM_TOTAL_GEMM);

    convert_x_kernel<<<M_TOTAL * H_DIM / 4 / 256, 256>>>(X);
    convert_w_kernel<<<dim3(H_DIM / 32, H_DIM / 32), dim3(32, 32)>>>(Wm);
    gemm_scores_kernel<<<MTILES * NTILES, GEMM_THREADS, SMEM_TOTAL_GEMM>>>(proj);
    output_kernel<<<M_TOTAL, 256>>>(X, out);
}

// round 11
// speedup vs baseline: 4.1577x; 2.0284x over previous
#include <cuda_runtime.h>
#include <cuda_fp16.h>
#include <cstdint>

// ---------------- problem constants ----------------
#define T_DIM   2048
#define B_DIM   16
#define H_DIM   1024
#define M_TOTAL (T_DIM * B_DIM)     // 32768 rows
#define W_ATT   3

// ---------------- GEMM tiling ----------------
#define TILE_M   128
#define TILE_N   256
#define KC       64                  // k elems per chunk
#define NCHUNKS  (H_DIM / KC)        // 16
#define NTILES   (H_DIM / TILE_N)    // 4
#define MTILES   (M_TOTAL / TILE_M)  // 256
#define GEMM_THREADS 512

// SMEM row stride: 64 fp16 = 128B data, padded to 144B (conflict-free ldmatrix)
#define ROWB     144
#define A_BYTES  (TILE_M * ROWB)     // 18432
#define B_BYTES  (TILE_N * ROWB)     // 36864
#define A_OFF    0
#define B_OFF    A_BYTES
#define STAGE_BYTES (A_BYTES + B_BYTES)   // 55296
#define PROJ_OFF (2 * STAGE_BYTES)        // 110592 (256 floats)
#define RED_OFF  (PROJ_OFF + 1024)        // 111616 (512 floats)
#define SMEM_TOTAL_GEMM (RED_OFF + 2048)  // 113664

// ---------------- global scratch ----------------
__device__ __half g_xh[(size_t)M_TOTAL * H_DIM];
__device__ __half g_whT[(size_t)H_DIM * H_DIM];   // [n][k]
__device__ float g_part[NTILES * M_TOTAL];

// ---------------- helpers ----------------
__device__ __forceinline__ uint32_t smem_u32(const void* p) {
    uint32_t a;
    asm("{ .reg .u64 t; cvta.to.shared.u64 t, %1; cvt.u32.u64 %0, t; }" : "=r"(a) : "l"(p));
    return a;
}

__device__ __forceinline__ void cp16(uint32_t dst, const void* src) {
    asm volatile("cp.async.cg.shared.global [%0], [%1], 16;\n"
                 :: "r"(dst), "l"(__cvta_generic_to_global(src)) : "memory");
}
#define CP_COMMIT() asm volatile("cp.async.commit_group;" ::: "memory")
#define CP_WAIT0()  asm volatile("cp.async.wait_group 0;"  ::: "memory")
#define CP_WAIT1()  asm volatile("cp.async.wait_group 1;"  ::: "memory")

__device__ __forceinline__ void ldsm_x4(uint32_t* r, uint32_t addr) {
    asm volatile("ldmatrix.sync.aligned.m8n8.x4.shared.b16 {%0,%1,%2,%3}, [%4];"
                 : "=r"(r[0]), "=r"(r[1]), "=r"(r[2]), "=r"(r[3]) : "r"(addr));
}

#define MMA_F16(c, a, b0v, b1v)                                               \
    asm volatile(                                                             \
        "mma.sync.aligned.m16n8k16.row.col.f32.f16.f16.f32 "                  \
        "{%0,%1,%2,%3}, {%4,%5,%6,%7}, {%8,%9}, {%0,%1,%2,%3};\n"             \
        : "+f"((c)[0]), "+f"((c)[1]), "+f"((c)[2]), "+f"((c)[3])              \
        : "r"((a)[0]), "r"((a)[1]), "r"((a)[2]), "r"((a)[3]),                 \
          "r"(b0v), "r"(b1v))

// ---------------- convert kernels ----------------
__global__ __launch_bounds__(256)
void convert_x_kernel(const float* __restrict__ X)
{
    size_t i = (size_t)blockIdx.x * 256 + threadIdx.x;    // float4 index
    float4 v = ((const float4*)X)[i];
    __half2 h0 = __float22half2_rn(make_float2(v.x, v.y));
    __half2 h1 = __float22half2_rn(make_float2(v.z, v.w));
    uint2 u;
    u.x = *(uint32_t*)&h0; u.y = *(uint32_t*)&h1;
    ((uint2*)g_xh)[i] = u;
}

__global__ __launch_bounds__(1024)
void convert_w_kernel(const float* __restrict__ W)
{
    __shared__ float t[32][33];
    int x = blockIdx.x * 32 + threadIdx.x;   // n
    int y = blockIdx.y * 32 + threadIdx.y;   // k
    t[threadIdx.y][threadIdx.x] = W[(size_t)y * H_DIM + x];
    __syncthreads();
    int n  = blockIdx.x * 32 + threadIdx.y;
    int kk = blockIdx.y * 32 + threadIdx.x;
    g_whT[(size_t)n * H_DIM + kk] = __float2half_rn(t[threadIdx.x][threadIdx.y]);
}

// ---------------- GEMM + fused tanh/proj epilogue ----------------
__device__ __forceinline__ void load_stage(uint32_t sbStage, int rowBase, int n0,
                                           int k0, int tid)
{
    // A: 128 rows x 8 x 16B
#pragma unroll
    for (int i = 0; i < 2; ++i) {
        int c = tid + i * 512;
        int row = c >> 3, q = c & 7;
        size_t off = (size_t)(rowBase + row) * H_DIM + k0 + q * 8;
        cp16(sbStage + A_OFF + row * ROWB + q * 16, g_xh + off);
    }
    // B: 256 rows x 8 x 16B
#pragma unroll
    for (int i = 0; i < 4; ++i) {
        int c = tid + i * 512;
        int row = c >> 3, q = c & 7;
        size_t off = (size_t)(n0 + row) * H_DIM + k0 + q * 8;
        cp16(sbStage + B_OFF + row * ROWB + q * 16, g_whT + off);
    }
}

__global__ __launch_bounds__(GEMM_THREADS, 1)
void gemm_scores_kernel(const float* __restrict__ proj)
{
    extern __shared__ __align__(16) char smem_raw[];
    const uint32_t sb = smem_u32(smem_raw);
    const int tid  = threadIdx.x;
    const int lane = tid & 31;
    const int wid  = tid >> 5;
    const int g    = lane >> 2;
    const int tg   = lane & 3;
    const int wm   = wid & 3;     // warp M (0..3): rows wm*32..+32
    const int wn   = wid >> 2;    // warp N (0..3): cols wn*64..+64

    const int mt = blockIdx.x >> 2;
    const int nt = blockIdx.x & 3;
    const int rowBase = mt * TILE_M;
    const int n0 = nt * TILE_N;

    float* projs = (float*)(smem_raw + PROJ_OFF);
    float* red   = (float*)(smem_raw + RED_OFF);
    if (tid < 256) projs[tid] = proj[n0 + tid];

    float C[2][8][4];
#pragma unroll
    for (int im = 0; im < 2; ++im)
#pragma unroll
        for (int in_ = 0; in_ < 8; ++in_)
#pragma unroll
            for (int e = 0; e < 4; ++e) C[im][in_][e] = 0.0f;

    // per-lane ldmatrix base addresses (within a stage)
    const uint32_t aBaseRel = (uint32_t)(A_OFF +
        (wm * 32 + (lane & 15)) * ROWB + (lane >> 4) * 16);
    const uint32_t bBaseRel = (uint32_t)(B_OFF +
        (wn * 64 + (lane & 7) + ((lane >> 4) & 1) * 8) * ROWB + ((lane >> 3) & 1) * 16);

    load_stage(sb, rowBase, n0, 0, tid);
    CP_COMMIT();
    load_stage(sb + STAGE_BYTES, rowBase, n0, KC, tid);
    CP_COMMIT();

#pragma unroll 1
    for (int k = 0; k < NCHUNKS; ++k) {
        if (k < NCHUNKS - 1) { CP_WAIT1(); } else { CP_WAIT0(); }
        __syncthreads();

        const uint32_t sBase = sb + (uint32_t)(k & 1) * STAGE_BYTES;
        const uint32_t aB = sBase + aBaseRel;
        const uint32_t bB = sBase + bBaseRel;

#pragma unroll
        for (int ks = 0; ks < 4; ++ks) {
            uint32_t ah[2][4];
            ldsm_x4(ah[0], aB + ks * 32);
            ldsm_x4(ah[1], aB + 16 * ROWB + ks * 32);
#pragma unroll
            for (int p = 0; p < 4; ++p) {
                uint32_t bh[4];
                ldsm_x4(bh, bB + p * (16 * ROWB) + ks * 32);
#pragma unroll
                for (int im = 0; im < 2; ++im) {
                    MMA_F16(C[im][2 * p],     ah[im], bh[0], bh[1]);
                    MMA_F16(C[im][2 * p + 1], ah[im], bh[2], bh[3]);
                }
            }
        }
        __syncthreads();
        if (k + 2 < NCHUNKS) {
            load_stage(sb + (uint32_t)(k & 1) * STAGE_BYTES, rowBase, n0, (k + 2) * KC, tid);
            CP_COMMIT();
        }
    }

    // ---- epilogue: tanh * proj, reduce over columns ----
    float acc[4] = {0.f, 0.f, 0.f, 0.f};
#pragma unroll
    for (int im = 0; im < 2; ++im) {
#pragma unroll
        for (int in_ = 0; in_ < 8; ++in_) {
            const int col = wn * 64 + in_ * 8 + 2 * tg;
            const float p0 = projs[col];
            const float p1 = projs[col + 1];
            acc[im * 2 + 0] += tanhf(C[im][in_][0]) * p0 + tanhf(C[im][in_][1]) * p1;
            acc[im * 2 + 1] += tanhf(C[im][in_][2]) * p0 + tanhf(C[im][in_][3]) * p1;
        }
    }
#pragma unroll
    for (int i = 0; i < 4; ++i) {
        acc[i] += __shfl_xor_sync(0xffffffff, acc[i], 1);
        acc[i] += __shfl_xor_sync(0xffffffff, acc[i], 2);
    }
    if (tg == 0) {
#pragma unroll
        for (int i = 0; i < 4; ++i) {
            const int im = i >> 1, half = i & 1;
            const int row = wm * 32 + im * 16 + half * 8 + g;
            red[wn * 128 + row] = acc[i];
        }
    }
    __syncthreads();
    if (tid < 128) {
        float s = red[tid] + red[128 + tid] + red[256 + tid] + red[384 + tid];
        g_part[nt * M_TOTAL + rowBase + tid] = s;
    }
}

// ---------------- output: sliding-window softmax + weighted sum ----------------
// Each block: one batch b, 8 consecutive timesteps. 3-row window kept in regs.
#define CHUNK_T 8
__global__ __launch_bounds__(256)
void output_kernel(const float* __restrict__ X, float* __restrict__ out)
{
    __shared__ float s_sc[CHUNK_T + 2];          // scores for t' = t0-3 .. t0+6
    __shared__ float s_w[CHUNK_T][3];            // softmax weights per output t

    const int blk = blockIdx.x;
    const int b   = blk & (B_DIM - 1);
    const int t0  = (blk >> 4) * CHUNK_T;
    const int tid = threadIdx.x;

    if (tid < CHUNK_T + 2) {
        const int tp = t0 - 3 + tid;
        float v = 0.0f;
        if (tp >= 0) {
            const int r = tp * B_DIM + b;
            v = g_part[r] + g_part[M_TOTAL + r]
              + g_part[2 * M_TOTAL + r] + g_part[3 * M_TOTAL + r];
        }
        s_sc[tid] = v;
    }
    __syncthreads();
    if (tid < CHUNK_T) {
        const int t = t0 + tid;
        if (t >= W_ATT) {
            const float s0 = s_sc[tid], s1 = s_sc[tid + 1], s2 = s_sc[tid + 2];
            const float m  = fmaxf(s0, fmaxf(s1, s2));
            const float e0 = expf(s0 - m);
            const float e1 = expf(s1 - m);
            const float e2 = expf(s2 - m);
            const float inv = 1.0f / (e0 + e1 + e2);
            s_w[tid][0] = e0 * inv;
            s_w[tid][1] = e1 * inv;
            s_w[tid][2] = e2 * inv;
        }
    }
    __syncthreads();

    const float4* Xi = (const float4*)X;
    float4* O = (float4*)out;

    float4 p3, p2, p1;
    if (t0 >= W_ATT) {
        p3 = Xi[(size_t)((t0 - 3) * B_DIM + b) * 256 + tid];
        p2 = Xi[(size_t)((t0 - 2) * B_DIM + b) * 256 + tid];
        p1 = Xi[(size_t)((t0 - 1) * B_DIM + b) * 256 + tid];
    }

#pragma unroll
    for (int j = 0; j < CHUNK_T; ++j) {
        const int t = t0 + j;
        const size_t ridx = (size_t)(t * B_DIM + b) * 256 + tid;
        const float4 cur = Xi[ridx];
        float4 o;
        if (t < W_ATT) {
            o = cur;
        } else {
            const float a0 = s_w[j][0], a1 = s_w[j][1], a2 = s_w[j][2];
            o.x = a0 * p3.x + a1 * p2.x + a2 * p1.x;
            o.y = a0 * p3.y + a1 * p2.y + a2 * p1.y;
            o.z = a0 * p3.z + a1 * p2.z + a2 * p1.z;
            o.w = a0 * p3.w + a1 * p2.w + a2 * p1.w;
        }
        O[ridx] = o;
        p3 = p2; p2 = p1; p1 = cur;
    }
}

// ---------------- launch ----------------
extern "C" void kernel_launch(void* const* d_in, const int* in_sizes, int n_in,
                              void* d_out, int out_size)
{
    const float* X    = (const float*)d_in[0];
    const float* Wm   = (const float*)d_in[1];
    const float* proj = (const float*)d_in[2];
    float* out        = (float*)d_out;

    cudaFuncSetAttribute(gemm_scores_kernel,
                         cudaFuncAttributeMaxDynamicSharedMemorySize,
                         SMEM_TOTAL_GEMM);

    convert_x_kernel<<<M_TOTAL * H_DIM / 4 / 256, 256>>>(X);
    convert_w_kernel<<<dim3(H_DIM / 32, H_DIM / 32), dim3(32, 32)>>>(Wm);
    gemm_scores_kernel<<<MTILES * NTILES, GEMM_THREADS, SMEM_TOTAL_GEMM>>>(proj);
    output_kernel<<<(T_DIM / CHUNK_T) * B_DIM, 256>>>(X, out);
}